// round 12
// baseline (speedup 1.0000x reference)
#include <cuda_runtime.h>

// SpatialTransformer: trilinear interpolation of vol at absolute coords trf.
// vol: [B=2, D=160, H=192, W=160, C=1] float32
// trf: [B=2, D,H,W, 3] float32 absolute coords (z,y,x = D,H,W)
// out: [B=2, D,H,W, 1] float32
//
// History:
//  R4 scalar 8 LDG/pt:            205.6us  (L1tex 90%, wavefront-bound)
//  R8 float4+extras, 2pt/thread:  178.9us  (L1 86.5%, occ 42%)
//  R9 float4+extras, 1pt/thread:  178.5us  (L1 84.6%, occ 66% -> occupancy NOT the limiter)
// R10+: eliminate the straddle extras entirely. A prep kernel expands vol
// into g_vol2[p] = (v[x], v[x+1 clamped]) float2 pairs. Every x-pair gather is
// then ONE 8B-aligned LDG.64 touching exactly one 128B line: 4 wavefronts per
// point, the floor for this access pattern. Clamp at x=159 falls out (wx0=0).

#define DD 160
#define HH 192
#define WW 160
#define PB (DD * HH * WW)       // 4,915,200 points per batch
#define NTOT (2 * PB)           // 9,830,400

// Expanded pair volume: 9,830,400 float2 = 78.6 MB (static device scratch).
__device__ float2 g_vol2[NTOT];

// ---- prep: vol2[b,z,y,x] = (v[b,z,y,x], v[b,z,y,min(x+1,159)]) ----------
__global__ __launch_bounds__(256)
void expand_kernel(const float* __restrict__ vol) {
    int idx = blockIdx.x * blockDim.x + threadIdx.x;
    if (idx >= NTOT) return;
    int x = idx % WW;                 // contiguous axis
    float a = __ldg(vol + idx);
    float b = (x < WW - 1) ? __ldg(vol + idx + 1) : a;
    g_vol2[idx] = make_float2(a, b);
}

// ---- gather: 4 x LDG.64 per point, no extras ------------------------------
__global__ __launch_bounds__(256)
void st_trilinear_kernel(const float* __restrict__ trf,
                         float* __restrict__ out) {
    int i = blockIdx.x * blockDim.x + threadIdx.x;
    if (i >= NTOT) return;

    const float MD = (float)(DD - 1);
    const float MH = (float)(HH - 1);
    const float MW = (float)(WW - 1);

    // batch volume offset without integer divide
    int voff = (i >= PB) ? PB : 0;

    int ti = 3 * i;   // 3*NTOT = 29.5M < 2^31
    float z = __ldg(trf + ti + 0);
    float y = __ldg(trf + ti + 1);
    float x = __ldg(trf + ti + 2);

    // Reference semantics:
    //   clipped = clip(loc,0,max); l0 = clip(floor(loc),0,max); l1 = clip(l0+1,0,max)
    //   w0 = l1 - clipped (pairs with l0); w1 = 1 - w0 (pairs with l1)
    float cz  = fminf(fmaxf(z, 0.f), MD);
    float z0f = fminf(fmaxf(floorf(z), 0.f), MD);
    float z1f = fminf(z0f + 1.f, MD);
    float wz0 = z1f - cz, wz1 = 1.f - wz0;

    float cy  = fminf(fmaxf(y, 0.f), MH);
    float y0f = fminf(fmaxf(floorf(y), 0.f), MH);
    float y1f = fminf(y0f + 1.f, MH);
    float wy0 = y1f - cy, wy1 = 1.f - wy0;

    float cx  = fminf(fmaxf(x, 0.f), MW);
    float x0f = fminf(fmaxf(floorf(x), 0.f), MW);
    float x1f = fminf(x0f + 1.f, MW);
    float wx0 = x1f - cx, wx1 = 1.f - wx0;
    // pair entry at ix0 holds (v[ix0], v[min(ix0+1,159)]) == (v[ix0], v[ix1]):
    // for ix0 < 159, ix1 = ix0+1; for ix0 = 159 (clamp), wx0 = 0 and .y = v[159].

    int iz0 = (int)z0f, iz1 = (int)z1f;
    int iy0 = (int)y0f, iy1 = (int)y1f;
    int ix0 = (int)x0f;

    int r00 = voff + iz0 * (HH * WW) + iy0 * WW + ix0;
    int r01 = voff + iz0 * (HH * WW) + iy1 * WW + ix0;
    int r10 = voff + iz1 * (HH * WW) + iy0 * WW + ix0;
    int r11 = voff + iz1 * (HH * WW) + iy1 * WW + ix0;

    // 4 independent 8B gathers, back-to-back; each touches exactly 1 line.
    float2 p00 = __ldg(&g_vol2[r00]);
    float2 p01 = __ldg(&g_vol2[r01]);
    float2 p10 = __ldg(&g_vol2[r10]);
    float2 p11 = __ldg(&g_vol2[r11]);

    float s00 = fmaf(wx0, p00.x, wx1 * p00.y);
    float s01 = fmaf(wx0, p01.x, wx1 * p01.y);
    float s10 = fmaf(wx0, p10.x, wx1 * p10.y);
    float s11 = fmaf(wx0, p11.x, wx1 * p11.y);

    float sz0 = fmaf(wy0, s00, wy1 * s01);
    float sz1 = fmaf(wy0, s10, wy1 * s11);
    out[i]    = fmaf(wz0, sz0, wz1 * sz1);
}

extern "C" void kernel_launch(void* const* d_in, const int* in_sizes, int n_in,
                              void* d_out, int out_size) {
    // Expected order: d_in[0] = vol (9,830,400), d_in[1] = trf (3x). Resolve
    // defensively by size so a swapped metadata order can't silently break.
    const float* vol = (const float*)d_in[0];
    const float* trf = (const float*)d_in[1];
    if (n_in >= 2 && in_sizes[0] > in_sizes[1]) {
        vol = (const float*)d_in[1];
        trf = (const float*)d_in[0];
    }
    float* out = (float*)d_out;

    int threads = 256;
    int blocks = (NTOT + threads - 1) / threads;
    expand_kernel<<<blocks, threads>>>(vol);
    st_trilinear_kernel<<<blocks, threads>>>(trf, out);
}

// round 14
// speedup vs baseline: 1.0105x; 1.0105x over previous
#include <cuda_runtime.h>

// SpatialTransformer: trilinear interpolation of vol at absolute coords trf.
// vol: [B=2, D=160, H=192, W=160, C=1] float32
// trf: [B=2, D,H,W, 3] float32 absolute coords (z,y,x = D,H,W)
// out: [B=2, D,H,W, 1] float32
//
// History:
//  R4  scalar 8 LDG/pt:              205.6us (L1tex 90%, wavefront-bound)
//  R8  float4+extras, 2pt/thread:    178.9us (L1 86.5%, occ 42%)
//  R9  float4+extras, 1pt/thread:    178.5us (L1 84.6%, occ 66%)
//  R12 pair-expand + LDG.64 gather:  184.7us = gather 150.9 (WIN, 4wf/pt) +
//                                    expand 33.8 (scalar expand too slow)
//  R13 vectorized expand + smem trf: infra failure (device busy), never ran
// R14 = R13 resubmitted:
//      (a) vectorize expand 4x (float4 in, 2x float4 out) -> ~16us;
//      (b) stage trf through smem in gather: 3 coalesced line-loads per warp
//          instead of 9 stride-3 wavefronts.

#define DD 160
#define HH 192
#define WW 160
#define PB (DD * HH * WW)       // 4,915,200 points per batch
#define NTOT (2 * PB)           // 9,830,400

// Expanded pair volume: 9,830,400 float2 = 78.6 MB (static device scratch).
__device__ float2 g_vol2[NTOT];

// ---- prep: vol2[b,z,y,x] = (v[x], v[min(x+1,159)]), 4 elems/thread -------
__global__ __launch_bounds__(256)
void expand_kernel(const float* __restrict__ vol) {
    int t = blockIdx.x * blockDim.x + threadIdx.x;   // 2,457,600 threads
    int idx4 = t * 4;                                 // multiple of 4
    if (idx4 >= NTOT) return;
    int x = idx4 % WW;                                // in {0,4,...,156}

    float4 v = __ldg(reinterpret_cast<const float4*>(vol + idx4));
    // neighbor of the last element: v[x+4], except row end (x==156 -> clamp)
    float v4 = (x < WW - 4) ? __ldg(vol + idx4 + 4) : v.w;

    float4 lo = make_float4(v.x, v.y, v.y, v.z);      // pairs (x), (x+1)
    float4 hi = make_float4(v.z, v.w, v.w, v4);       // pairs (x+2), (x+3)
    float4* dst = reinterpret_cast<float4*>(&g_vol2[idx4]);  // 32B-aligned
    dst[0] = lo;
    dst[1] = hi;
}

// ---- gather: 4 x LDG.64 per point + smem-staged trf -----------------------
__global__ __launch_bounds__(256)
void st_trilinear_kernel(const float* __restrict__ trf,
                         float* __restrict__ out) {
    __shared__ float s[768];          // 256 points * 3 coords
    int tid = threadIdx.x;
    int i = blockIdx.x * 256 + tid;   // NTOT % 256 == 0: no tail anywhere

    // Stage this block's trf slice with 3 fully-coalesced loads per thread:
    // each warp-load touches exactly one 128B line (1 wavefront vs 3).
    int base = blockIdx.x * 768;
    s[tid]       = __ldg(trf + base + tid);
    s[tid + 256] = __ldg(trf + base + tid + 256);
    s[tid + 512] = __ldg(trf + base + tid + 512);
    __syncthreads();

    // stride-3 smem reads: 3 coprime to 32 banks -> conflict-free
    float z = s[3 * tid + 0];
    float y = s[3 * tid + 1];
    float x = s[3 * tid + 2];

    const float MD = (float)(DD - 1);
    const float MH = (float)(HH - 1);
    const float MW = (float)(WW - 1);

    int voff = (i >= PB) ? PB : 0;    // batch offset, no divide

    // Reference semantics:
    //   clipped = clip(loc,0,max); l0 = clip(floor(loc),0,max); l1 = clip(l0+1,0,max)
    //   w0 = l1 - clipped (pairs with l0); w1 = 1 - w0 (pairs with l1)
    float cz  = fminf(fmaxf(z, 0.f), MD);
    float z0f = fminf(fmaxf(floorf(z), 0.f), MD);
    float z1f = fminf(z0f + 1.f, MD);
    float wz0 = z1f - cz, wz1 = 1.f - wz0;

    float cy  = fminf(fmaxf(y, 0.f), MH);
    float y0f = fminf(fmaxf(floorf(y), 0.f), MH);
    float y1f = fminf(y0f + 1.f, MH);
    float wy0 = y1f - cy, wy1 = 1.f - wy0;

    float cx  = fminf(fmaxf(x, 0.f), MW);
    float x0f = fminf(fmaxf(floorf(x), 0.f), MW);
    float x1f = fminf(x0f + 1.f, MW);
    float wx0 = x1f - cx, wx1 = 1.f - wx0;
    // pair entry at ix0 holds (v[ix0], v[min(ix0+1,159)]) == (v[ix0], v[ix1]):
    // interior: ix1 = ix0+1; clamp ix0=159: wx0 = 0 and .y = v[159].

    int iz0 = (int)z0f, iz1 = (int)z1f;
    int iy0 = (int)y0f, iy1 = (int)y1f;
    int ix0 = (int)x0f;

    int r00 = voff + iz0 * (HH * WW) + iy0 * WW + ix0;
    int r01 = voff + iz0 * (HH * WW) + iy1 * WW + ix0;
    int r10 = voff + iz1 * (HH * WW) + iy0 * WW + ix0;
    int r11 = voff + iz1 * (HH * WW) + iy1 * WW + ix0;

    // 4 independent 8B gathers, back-to-back; each touches exactly 1 line.
    float2 p00 = __ldg(&g_vol2[r00]);
    float2 p01 = __ldg(&g_vol2[r01]);
    float2 p10 = __ldg(&g_vol2[r10]);
    float2 p11 = __ldg(&g_vol2[r11]);

    float s00 = fmaf(wx0, p00.x, wx1 * p00.y);
    float s01 = fmaf(wx0, p01.x, wx1 * p01.y);
    float s10 = fmaf(wx0, p10.x, wx1 * p10.y);
    float s11 = fmaf(wx0, p11.x, wx1 * p11.y);

    float sz0 = fmaf(wy0, s00, wy1 * s01);
    float sz1 = fmaf(wy0, s10, wy1 * s11);
    out[i]    = fmaf(wz0, sz0, wz1 * sz1);
}

extern "C" void kernel_launch(void* const* d_in, const int* in_sizes, int n_in,
                              void* d_out, int out_size) {
    // Expected order: d_in[0] = vol (9,830,400), d_in[1] = trf (3x). Resolve
    // defensively by size so a swapped metadata order can't silently break.
    const float* vol = (const float*)d_in[0];
    const float* trf = (const float*)d_in[1];
    if (n_in >= 2 && in_sizes[0] > in_sizes[1]) {
        vol = (const float*)d_in[1];
        trf = (const float*)d_in[0];
    }
    float* out = (float*)d_out;

    int threads = 256;
    int expand_blocks = (NTOT / 4 + threads - 1) / threads;   // 9600
    int gather_blocks = NTOT / threads;                       // 38400, exact
    expand_kernel<<<expand_blocks, threads>>>(vol);
    st_trilinear_kernel<<<gather_blocks, threads>>>(trf, out);
}